// round 2
// baseline (speedup 1.0000x reference)
#include <cuda_runtime.h>
#include <math.h>

#define Nn 100000
#define Emax 1600000
#define ETmax (Emax + Nn)
#define BN_EPS 1e-5f
#define LRELU 0.2f

// ---- scratch (static device globals; no allocation) ----
__device__ float g_H[Nn * 64];        // transformed features (pre-aggregation)
__device__ float g_X[Nn * 64];        // post-layer features
__device__ float g_alS[Nn * 4];
__device__ float g_alD[Nn * 4];
__device__ int   g_deg[Nn];
__device__ int   g_rowoff[Nn + 1];
__device__ int   g_cursor[Nn];
__device__ int   g_adj[ETmax];
__device__ float g_pooled[64];

// ---------------- CSR build ----------------
__global__ void __launch_bounds__(256) k_init() {
    int i = blockIdx.x * blockDim.x + threadIdx.x;
    if (i < Nn) g_deg[i] = 1;          // self-loop
    if (i < 64) g_pooled[i] = 0.f;
}

__global__ void __launch_bounds__(256) k_count(const int* __restrict__ dst, int E) {
    int i = blockIdx.x * blockDim.x + threadIdx.x;
    if (i < E) atomicAdd(&g_deg[dst[i]], 1);
}

__global__ void __launch_bounds__(1024) k_scan() {
    const int T = 1024;
    const int CH = (Nn + T - 1) / T;
    __shared__ int sh[T];
    int tid = threadIdx.x;
    int base = tid * CH;
    int total = 0;
#pragma unroll 1
    for (int j = 0; j < CH; j++) {
        int idx = base + j;
        if (idx < Nn) total += g_deg[idx];
    }
    sh[tid] = total;
    __syncthreads();
#pragma unroll 1
    for (int off = 1; off < T; off <<= 1) {
        int v = 0;
        if (tid >= off) v = sh[tid - off];
        __syncthreads();
        sh[tid] += v;
        __syncthreads();
    }
    int run = sh[tid] - total;   // exclusive base
#pragma unroll 1
    for (int j = 0; j < CH; j++) {
        int idx = base + j;
        if (idx < Nn) { g_rowoff[idx] = run; run += g_deg[idx]; }
    }
    if (tid == T - 1) g_rowoff[Nn] = sh[T - 1];
}

__global__ void __launch_bounds__(256) k_cursor() {
    int i = blockIdx.x * blockDim.x + threadIdx.x;
    if (i < Nn) g_cursor[i] = g_rowoff[i];
}

__global__ void __launch_bounds__(256) k_fill(const int* __restrict__ src,
                                              const int* __restrict__ dst, int E) {
    int i = blockIdx.x * blockDim.x + threadIdx.x;
    int tot = E + Nn;
    if (i >= tot) return;
    int s, d;
    if (i < E) { s = src[i]; d = dst[i]; }
    else       { s = i - E; d = s; }
    int p = atomicAdd(&g_cursor[d], 1);
    g_adj[p] = s;
}

// ---------------- linear + attention-logit kernel ----------------
// thread-per-node, W transposed in smem, x staged through smem.
template <int IN, int HEADS>
__global__ void __launch_bounds__(96) k_lin(const float* __restrict__ xin,
                                            const float* __restrict__ W,
                                            const float* __restrict__ asrc,
                                            const float* __restrict__ adst) {
    constexpr int TB = 96;
    constexpr int XS = (IN == 64) ? 65 : IN;
    __shared__ float Wsh[64 * IN];
    __shared__ float xsh[TB * XS];
    int tid = threadIdx.x;
    int vbase = blockIdx.x * TB;

    for (int i = tid; i < 64 * IN; i += TB) {
        int c = i / IN, k = i % IN;
        Wsh[k * 64 + c] = W[i];          // transposed: Wsh[k][c]
    }
    const float* srcp = (IN == 64) ? (const float*)g_X : xin;
    for (int i = tid; i < TB * IN; i += TB) {
        int node = i / IN, k = i % IN;
        int v = vbase + node;
        xsh[node * XS + k] = (v < Nn) ? srcp[(size_t)v * IN + k] : 0.f;
    }
    __syncthreads();

    float acc[64];
#pragma unroll
    for (int c = 0; c < 64; c++) acc[c] = 0.f;

#pragma unroll 4
    for (int k = 0; k < IN; k++) {
        float xk = xsh[tid * XS + k];
        const float4* W4 = (const float4*)(Wsh + k * 64);
#pragma unroll
        for (int c4 = 0; c4 < 16; c4++) {
            float4 w = W4[c4];
            acc[c4 * 4 + 0] += w.x * xk;
            acc[c4 * 4 + 1] += w.y * xk;
            acc[c4 * 4 + 2] += w.z * xk;
            acc[c4 * 4 + 3] += w.w * xk;
        }
    }

    int v = vbase + tid;
    if (v < Nn) {
        constexpr int C = 64 / HEADS;
#pragma unroll
        for (int h = 0; h < HEADS; h++) {
            float s1 = 0.f, s2 = 0.f;
#pragma unroll
            for (int j = 0; j < C; j++) {
                float t = acc[h * C + j];
                s1 += t * asrc[h * C + j];
                s2 += t * adst[h * C + j];
            }
            g_alS[(size_t)v * HEADS + h] = s1;
            g_alD[(size_t)v * HEADS + h] = s2;
        }
    }

    __syncthreads();
    if (IN == 64) {
        // stage through smem for coalesced store
#pragma unroll
        for (int c = 0; c < 64; c++) xsh[tid * 65 + c] = acc[c];
        __syncthreads();
        for (int i = tid; i < TB * 64; i += TB) {
            int node = i / 64, c = i % 64;
            int vv = vbase + node;
            if (vv < Nn) g_H[(size_t)vv * 64 + c] = xsh[node * 65 + c];
        }
    } else {
        if (v < Nn) {
            float4* o = (float4*)(g_H + (size_t)v * 64);
#pragma unroll
            for (int c = 0; c < 64; c += 4)
                o[c >> 2] = make_float4(acc[c], acc[c + 1], acc[c + 2], acc[c + 3]);
        }
    }
}

// ---------------- aggregation: warp per dst node, fused softmax+BN(+ELU) ----------------
template <int HEADS, bool ELU>
__global__ void __launch_bounds__(256) k_agg(const float* __restrict__ bias,
                      const float* __restrict__ gamma, const float* __restrict__ beta,
                      const float* __restrict__ mean,  const float* __restrict__ var) {
    int wid = (blockIdx.x * blockDim.x + threadIdx.x) >> 5;
    int lane = threadIdx.x & 31;
    if (wid >= Nn) return;
    int v = wid;
    int start = g_rowoff[v], end = g_rowoff[v + 1];

    float alDv[HEADS];
#pragma unroll
    for (int h = 0; h < HEADS; h++) alDv[h] = g_alD[(size_t)v * HEADS + h];

    // pass 1: per-head max over incoming edges (lanes strided)
    float m[HEADS];
#pragma unroll
    for (int h = 0; h < HEADS; h++) m[h] = -3.4e38f;
    for (int i = start + lane; i < end; i += 32) {
        int s = g_adj[i];
        if (HEADS == 4) {
            float4 a4 = ((const float4*)g_alS)[s];
            float e0 = a4.x + alDv[0]; e0 = e0 > 0.f ? e0 : LRELU * e0;
            float e1 = a4.y + alDv[1]; e1 = e1 > 0.f ? e1 : LRELU * e1;
            float e2 = a4.z + alDv[2]; e2 = e2 > 0.f ? e2 : LRELU * e2;
            float e3 = a4.w + alDv[3]; e3 = e3 > 0.f ? e3 : LRELU * e3;
            m[0] = fmaxf(m[0], e0); m[1] = fmaxf(m[1], e1);
            m[2] = fmaxf(m[2], e2); m[3] = fmaxf(m[3], e3);
        } else {
            float e = g_alS[s] + alDv[0];
            e = e > 0.f ? e : LRELU * e;
            m[0] = fmaxf(m[0], e);
        }
    }
#pragma unroll
    for (int h = 0; h < HEADS; h++)
        for (int off = 16; off; off >>= 1)
            m[h] = fmaxf(m[h], __shfl_xor_sync(0xffffffffu, m[h], off));

    // lane-local head values (lane h holds head h's alD / m)
    float alD_l, m_l;
    if (HEADS == 4) {
        alD_l = alDv[0]; m_l = m[0];
        if (lane == 1) { alD_l = alDv[1]; m_l = m[1]; }
        else if (lane == 2) { alD_l = alDv[2]; m_l = m[2]; }
        else if (lane == 3) { alD_l = alDv[3]; m_l = m[3]; }
    } else {
        alD_l = alDv[0]; m_l = m[0];
    }
    int h0 = (HEADS == 4) ? (lane >> 4) : 0;        // head of channel `lane`
    int h1 = (HEADS == 4) ? h0 + 2 : 0;             // head of channel `lane+32`

    // pass 2: weighted accumulation (edges sequential, lanes = channels)
    float acc0 = 0.f, acc1 = 0.f, ssum = 0.f;
    for (int i = start; i < end; i++) {
        int s = g_adj[i];
        float w = 0.f;
        if (lane < HEADS) {
            float e = g_alS[(size_t)s * HEADS + lane] + alD_l;
            e = e > 0.f ? e : LRELU * e;
            w = expf(e - m_l);
        }
        ssum += w;
        float w0 = __shfl_sync(0xffffffffu, w, h0);
        float w1 = __shfl_sync(0xffffffffu, w, h1);
        const float* hrow = g_H + (size_t)s * 64;
        acc0 += w0 * hrow[lane];
        acc1 += w1 * hrow[lane + 32];
    }
    float s0 = __shfl_sync(0xffffffffu, ssum, h0) + 1e-16f;
    float s1 = __shfl_sync(0xffffffffu, ssum, h1) + 1e-16f;

    float r0 = acc0 / s0 + bias[lane];
    float r1 = acc1 / s1 + bias[lane + 32];
    // BN (eval)
    r0 = (r0 - mean[lane]) * rsqrtf(var[lane] + BN_EPS) * gamma[lane] + beta[lane];
    r1 = (r1 - mean[lane + 32]) * rsqrtf(var[lane + 32] + BN_EPS) * gamma[lane + 32] + beta[lane + 32];
    if (ELU) {
        r0 = r0 > 0.f ? r0 : (expf(r0) - 1.f);
        r1 = r1 > 0.f ? r1 : (expf(r1) - 1.f);
    }
    g_X[(size_t)v * 64 + lane]      = r0;
    g_X[(size_t)v * 64 + lane + 32] = r1;
}

// ---------------- mean pool + heads ----------------
__global__ void __launch_bounds__(64) k_pool() {
    int c = threadIdx.x;    // 64 threads
    float s = 0.f;
    for (int v = blockIdx.x; v < Nn; v += gridDim.x)
        s += g_X[(size_t)v * 64 + c];
    atomicAdd(&g_pooled[c], s);
}

__global__ void __launch_bounds__(64) k_head(const float* __restrict__ cw1, const float* __restrict__ cb1,
                       const float* __restrict__ cw2, const float* __restrict__ cb2,
                       const float* __restrict__ rw1, const float* __restrict__ rb1,
                       const float* __restrict__ rw2, const float* __restrict__ rb2,
                       float* __restrict__ out) {
    __shared__ float pm[64], hc[32], hr[32];
    int t = threadIdx.x;    // 64 threads
    if (t < 64) pm[t] = g_pooled[t] * (1.0f / (float)Nn);
    __syncthreads();
    if (t < 32) {
        float sc = cb1[t], sr = rb1[t];
        for (int k = 0; k < 64; k++) {
            sc += cw1[t * 64 + k] * pm[k];
            sr += rw1[t * 64 + k] * pm[k];
        }
        hc[t] = fmaxf(sc, 0.f);
        hr[t] = fmaxf(sr, 0.f);
    }
    __syncthreads();
    if (t < 3) {
        float s = cb2[t];
        for (int k = 0; k < 32; k++) s += cw2[t * 32 + k] * hc[k];
        out[t] = s;
    }
    if (t == 3) {
        float s = rb2[0];
        for (int k = 0; k < 32; k++) s += rw2[k] * hr[k];
        out[3] = s;
    }
}

// ---------------- launch ----------------
extern "C" void kernel_launch(void* const* d_in, const int* in_sizes, int n_in,
                              void* d_out, int out_size) {
    const float* x   = (const float*)d_in[0];
    const int*   ei  = (const int*)d_in[1];
    int E = in_sizes[1] / 2;
    if (E > Emax) E = Emax;
    const int* srcA = ei;
    const int* dstA = ei + E;
    const float* W1  = (const float*)d_in[2];
    const float* a1s = (const float*)d_in[3];
    const float* a1d = (const float*)d_in[4];
    const float* b1  = (const float*)d_in[5];
    const float* W2  = (const float*)d_in[6];
    const float* a2s = (const float*)d_in[7];
    const float* a2d = (const float*)d_in[8];
    const float* b2  = (const float*)d_in[9];
    const float* W3  = (const float*)d_in[10];
    const float* a3s = (const float*)d_in[11];
    const float* a3d = (const float*)d_in[12];
    const float* b3  = (const float*)d_in[13];
    const float* bg  = (const float*)d_in[14];
    const float* bb  = (const float*)d_in[15];
    const float* bm  = (const float*)d_in[16];
    const float* bv  = (const float*)d_in[17];
    const float* cw1 = (const float*)d_in[18];
    const float* cb1 = (const float*)d_in[19];
    const float* cw2 = (const float*)d_in[20];
    const float* cb2 = (const float*)d_in[21];
    const float* rw1 = (const float*)d_in[22];
    const float* rb1 = (const float*)d_in[23];
    const float* rw2 = (const float*)d_in[24];
    const float* rb2 = (const float*)d_in[25];
    float* out = (float*)d_out;

    // CSR build (every call; deterministic work)
    k_init<<<(Nn + 255) / 256, 256>>>();
    k_count<<<(E + 255) / 256, 256>>>(dstA, E);
    k_scan<<<1, 1024>>>();
    k_cursor<<<(Nn + 255) / 256, 256>>>();
    k_fill<<<(E + Nn + 255) / 256, 256>>>(srcA, dstA, E);

    int linGrid = (Nn + 95) / 96;
    int aggGrid = (Nn * 32 + 255) / 256;

    // layer 1
    k_lin<5, 4><<<linGrid, 96>>>(x, W1, a1s, a1d);
    k_agg<4, true><<<aggGrid, 256>>>(b1, bg + 0,  bb + 0,  bm + 0,  bv + 0);
    // layer 2
    k_lin<64, 4><<<linGrid, 96>>>(nullptr, W2, a2s, a2d);
    k_agg<4, true><<<aggGrid, 256>>>(b2, bg + 64, bb + 64, bm + 64, bv + 64);
    // layer 3
    k_lin<64, 1><<<linGrid, 96>>>(nullptr, W3, a3s, a3d);
    k_agg<1, false><<<aggGrid, 256>>>(b3, bg + 128, bb + 128, bm + 128, bv + 128);

    // pool + heads
    k_pool<<<256, 64>>>();
    k_head<<<1, 64>>>(cw1, cb1, cw2, cb2, rw1, rb1, rw2, rb2, out);
}

// round 4
// speedup vs baseline: 1.1606x; 1.1606x over previous
#include <cuda_runtime.h>
#include <math.h>

#define Nn 100000
#define Emax 1600000
#define ETmax (Emax + Nn)
#define BN_EPS 1e-5f
#define LRELU 0.2f

// ---- scratch (static device globals; no allocation) ----
__device__ float g_H[Nn * 64];        // transformed features (pre-aggregation)
__device__ float g_X[Nn * 64];        // post-layer features
__device__ float g_alS[Nn * 4];
__device__ float g_alD[Nn * 4];
__device__ int   g_deg[Nn];
__device__ int   g_rowoff[Nn + 1];
__device__ int   g_cursor[Nn];
__device__ int   g_adj[ETmax];
__device__ float g_pooled[64];
__device__ unsigned g_mEnc[12];       // order-encoded per-layer per-head global alS max

// order-preserving float<->uint encoding (for atomicMax on floats incl. negatives)
__device__ __forceinline__ unsigned encF(float f) {
    unsigned u = __float_as_uint(f);
    return (u & 0x80000000u) ? ~u : (u | 0x80000000u);
}
__device__ __forceinline__ float decF(unsigned e) {
    unsigned u = (e & 0x80000000u) ? (e & 0x7FFFFFFFu) : ~e;
    return __uint_as_float(u);
}

// ---------------- CSR build ----------------
__global__ void __launch_bounds__(256) k_init() {
    int i = blockIdx.x * blockDim.x + threadIdx.x;
    if (i < Nn) g_deg[i] = 1;          // self-loop
    if (i < 64) g_pooled[i] = 0.f;
    if (i < 12) g_mEnc[i] = 0u;        // below any real encoded float
}

__global__ void __launch_bounds__(256) k_count(const int* __restrict__ dst, int E) {
    int i = blockIdx.x * blockDim.x + threadIdx.x;
    if (i < E) atomicAdd(&g_deg[dst[i]], 1);
}

__global__ void __launch_bounds__(1024) k_scan(int total) {
    const int T = 1024;
    const int CH = (Nn + T - 1) / T;
    __shared__ int sh[T];
    int tid = threadIdx.x;
    int base = tid * CH;
    int tsum = 0;
#pragma unroll 4
    for (int j = 0; j < CH; j++) {
        int idx = base + j;
        if (idx < Nn) tsum += g_deg[idx];
    }
    sh[tid] = tsum;
    __syncthreads();
#pragma unroll 1
    for (int off = 1; off < T; off <<= 1) {
        int v = 0;
        if (tid >= off) v = sh[tid - off];
        __syncthreads();
        sh[tid] += v;
        __syncthreads();
    }
    int run = sh[tid] - tsum;   // exclusive base
#pragma unroll 4
    for (int j = 0; j < CH; j++) {
        int idx = base + j;
        if (idx < Nn) {
            g_rowoff[idx] = run;
            g_cursor[idx] = run;     // fused cursor init
            run += g_deg[idx];
        }
    }
    if (tid == 0) g_rowoff[Nn] = total;
}

__global__ void __launch_bounds__(256) k_fill(const int* __restrict__ src,
                                              const int* __restrict__ dst, int E) {
    int i = blockIdx.x * blockDim.x + threadIdx.x;
    int tot = E + Nn;
    if (i >= tot) return;
    int s, d;
    if (i < E) { s = src[i]; d = dst[i]; }
    else       { s = i - E; d = s; }
    int p = atomicAdd(&g_cursor[d], 1);
    g_adj[p] = s;
}

// ---------------- linear + attention-logit kernel (f32x2 packed FMA) ----------------
template <int IN, int HEADS>
__global__ void __launch_bounds__(128) k_lin(const float* __restrict__ xin,
                                             const float* __restrict__ W,
                                             const float* __restrict__ asrc,
                                             const float* __restrict__ adst,
                                             int layer) {
    constexpr int TB = 128;
    constexpr int XS = (IN == 64) ? 65 : IN;
    __shared__ __align__(16) float Wsh[64 * IN];
    __shared__ __align__(16) float xsh[TB * ((IN == 64) ? 65 : IN)];
    int tid = threadIdx.x;
    int lane = tid & 31;
    int vbase = blockIdx.x * TB;

    for (int i = tid; i < 64 * IN; i += TB) {
        int c = i / IN, k = i % IN;
        Wsh[k * 64 + c] = W[i];          // transposed: Wsh[k][c]
    }
    const float* srcp = (IN == 64) ? (const float*)g_X : xin;
    for (int i = tid; i < TB * IN; i += TB) {
        int node = i / IN, k = i % IN;
        int v = vbase + node;
        xsh[node * XS + k] = (v < Nn) ? srcp[(size_t)v * IN + k] : 0.f;
    }
    __syncthreads();

    unsigned long long acc2[32];
#pragma unroll
    for (int j = 0; j < 32; j++) acc2[j] = 0ull;   // bits 0 == {+0.f,+0.f}

#pragma unroll 4
    for (int k = 0; k < IN; k++) {
        float xk = xsh[tid * XS + k];
        unsigned long long xk2;
        asm("mov.b64 %0, {%1, %1};" : "=l"(xk2) : "f"(xk));
        const unsigned long long* Wp = (const unsigned long long*)(Wsh + k * 64);
#pragma unroll
        for (int j = 0; j < 32; j++) {
            asm("fma.rn.f32x2 %0, %1, %2, %0;" : "+l"(acc2[j]) : "l"(Wp[j]), "l"(xk2));
        }
    }

    float accf[64];
#pragma unroll
    for (int j = 0; j < 32; j++) {
        asm("mov.b64 {%0, %1}, %2;" : "=f"(accf[2 * j]), "=f"(accf[2 * j + 1]) : "l"(acc2[j]));
    }

    int v = vbase + tid;
    bool valid = (v < Nn);
    constexpr int C = 64 / HEADS;
    float mx[HEADS];
#pragma unroll
    for (int h = 0; h < HEADS; h++) {
        float s1 = 0.f, s2 = 0.f;
#pragma unroll
        for (int j = 0; j < C; j++) {
            float t = accf[h * C + j];
            s1 += t * asrc[h * C + j];
            s2 += t * adst[h * C + j];
        }
        if (valid) {
            g_alS[(size_t)v * HEADS + h] = s1;
            g_alD[(size_t)v * HEADS + h] = s2;
        }
        mx[h] = valid ? s1 : -3.4e38f;
    }
    // warp-reduce max per head, one atomic per warp per head
#pragma unroll
    for (int h = 0; h < HEADS; h++) {
#pragma unroll
        for (int off = 16; off; off >>= 1)
            mx[h] = fmaxf(mx[h], __shfl_xor_sync(0xffffffffu, mx[h], off));
        if (lane == 0) atomicMax(&g_mEnc[layer * 4 + h], encF(mx[h]));
    }

    __syncthreads();
    if (IN == 64) {
        // stage through smem for coalesced store
#pragma unroll
        for (int c = 0; c < 64; c++) xsh[tid * 65 + c] = accf[c];
        __syncthreads();
        for (int i = tid; i < TB * 64; i += TB) {
            int node = i >> 6, c = i & 63;
            int vv = vbase + node;
            if (vv < Nn) g_H[(size_t)vv * 64 + c] = xsh[node * 65 + c];
        }
    } else {
        if (valid) {
            float4* o = (float4*)(g_H + (size_t)v * 64);
#pragma unroll
            for (int c = 0; c < 64; c += 4)
                o[c >> 2] = make_float4(accf[c], accf[c + 1], accf[c + 2], accf[c + 3]);
        }
    }
}

// ---------------- aggregation: warp/node, single pass, chunked weights ----------------
template <int HEADS, bool ELU>
__global__ void __launch_bounds__(256) k_agg(const float* __restrict__ bias,
                      const float* __restrict__ gamma, const float* __restrict__ beta,
                      const float* __restrict__ mean,  const float* __restrict__ var,
                      int layer) {
    __shared__ float ws[8][HEADS == 4 ? 128 : 32];
    int wslot = threadIdx.x >> 5;
    int lane = threadIdx.x & 31;
    int v = (blockIdx.x * blockDim.x + threadIdx.x) >> 5;
    if (v >= Nn) return;
    int start = g_rowoff[v], end = g_rowoff[v + 1];

    float acc0 = 0.f, acc1 = 0.f;

    if (HEADS == 4) {
        float4 alD4 = ((const float4*)g_alD)[v];
        float4 mv4;
        mv4.x = decF(g_mEnc[layer * 4 + 0]) + alD4.x; mv4.x = mv4.x > 0.f ? mv4.x : LRELU * mv4.x;
        mv4.y = decF(g_mEnc[layer * 4 + 1]) + alD4.y; mv4.y = mv4.y > 0.f ? mv4.y : LRELU * mv4.y;
        mv4.z = decF(g_mEnc[layer * 4 + 2]) + alD4.z; mv4.z = mv4.z > 0.f ? mv4.z : LRELU * mv4.z;
        mv4.w = decF(g_mEnc[layer * 4 + 3]) + alD4.w; mv4.w = mv4.w > 0.f ? mv4.w : LRELU * mv4.w;

        int h0 = lane >> 4;          // head of channel `lane`
        int h1 = h0 + 2;             // head of channel `lane+32`
        float4 sum4 = make_float4(0.f, 0.f, 0.f, 0.f);

        for (int base = start; base < end; base += 32) {
            int n = end - base; if (n > 32) n = 32;
            int sl = g_adj[base + (lane < n ? lane : 0)];
            float4 a4 = ((const float4*)g_alS)[sl];
            float e0 = a4.x + alD4.x; e0 = e0 > 0.f ? e0 : LRELU * e0;
            float e1 = a4.y + alD4.y; e1 = e1 > 0.f ? e1 : LRELU * e1;
            float e2 = a4.z + alD4.z; e2 = e2 > 0.f ? e2 : LRELU * e2;
            float e3 = a4.w + alD4.w; e3 = e3 > 0.f ? e3 : LRELU * e3;
            float w0 = __expf(e0 - mv4.x), w1 = __expf(e1 - mv4.y);
            float w2 = __expf(e2 - mv4.z), w3 = __expf(e3 - mv4.w);
            if (lane >= n) { w0 = w1 = w2 = w3 = 0.f; }
            sum4.x += w0; sum4.y += w1; sum4.z += w2; sum4.w += w3;
            *(float4*)&ws[wslot][lane * 4] = make_float4(w0, w1, w2, w3);
            __syncwarp();
#pragma unroll 4
            for (int j = 0; j < n; j++) {
                int s = __shfl_sync(0xffffffffu, sl, j);
                float wa = ws[wslot][j * 4 + h0];
                float wb = ws[wslot][j * 4 + h1];
                const float* hr = g_H + (size_t)s * 64;
                acc0 += wa * hr[lane];
                acc1 += wb * hr[lane + 32];
            }
            __syncwarp();
        }
#pragma unroll
        for (int off = 16; off; off >>= 1) {
            sum4.x += __shfl_xor_sync(0xffffffffu, sum4.x, off);
            sum4.y += __shfl_xor_sync(0xffffffffu, sum4.y, off);
            sum4.z += __shfl_xor_sync(0xffffffffu, sum4.z, off);
            sum4.w += __shfl_xor_sync(0xffffffffu, sum4.w, off);
        }
        float s0 = ((lane < 16) ? sum4.x : sum4.y) + 1e-16f;
        float s1 = ((lane < 16) ? sum4.z : sum4.w) + 1e-16f;
        acc0 /= s0;
        acc1 /= s1;
    } else {
        float alD = g_alD[v];
        float mv = decF(g_mEnc[layer * 4]) + alD; mv = mv > 0.f ? mv : LRELU * mv;
        float ssum = 0.f;
        for (int base = start; base < end; base += 32) {
            int n = end - base; if (n > 32) n = 32;
            int sl = g_adj[base + (lane < n ? lane : 0)];
            float e = g_alS[sl] + alD; e = e > 0.f ? e : LRELU * e;
            float w = __expf(e - mv);
            if (lane >= n) w = 0.f;
            ssum += w;
            ws[wslot][lane] = w;
            __syncwarp();
#pragma unroll 4
            for (int j = 0; j < n; j++) {
                int s = __shfl_sync(0xffffffffu, sl, j);
                float wa = ws[wslot][j];
                const float* hr = g_H + (size_t)s * 64;
                acc0 += wa * hr[lane];
                acc1 += wa * hr[lane + 32];
            }
            __syncwarp();
        }
#pragma unroll
        for (int off = 16; off; off >>= 1)
            ssum += __shfl_xor_sync(0xffffffffu, ssum, off);
        float s0 = ssum + 1e-16f;
        acc0 /= s0;
        acc1 /= s0;
    }

    float r0 = acc0 + bias[lane];
    float r1 = acc1 + bias[lane + 32];
    // BN (eval)
    r0 = (r0 - mean[lane]) * rsqrtf(var[lane] + BN_EPS) * gamma[lane] + beta[lane];
    r1 = (r1 - mean[lane + 32]) * rsqrtf(var[lane + 32] + BN_EPS) * gamma[lane + 32] + beta[lane + 32];
    if (ELU) {
        r0 = r0 > 0.f ? r0 : (expf(r0) - 1.f);
        r1 = r1 > 0.f ? r1 : (expf(r1) - 1.f);
    }
    g_X[(size_t)v * 64 + lane]      = r0;
    g_X[(size_t)v * 64 + lane + 32] = r1;
}

// ---------------- mean pool + heads ----------------
__global__ void __launch_bounds__(64) k_pool() {
    int c = threadIdx.x;    // 64 threads
    float s = 0.f;
#pragma unroll 4
    for (int v = blockIdx.x; v < Nn; v += gridDim.x)
        s += g_X[(size_t)v * 64 + c];
    atomicAdd(&g_pooled[c], s);
}

__global__ void __launch_bounds__(64) k_head(const float* __restrict__ cw1, const float* __restrict__ cb1,
                       const float* __restrict__ cw2, const float* __restrict__ cb2,
                       const float* __restrict__ rw1, const float* __restrict__ rb1,
                       const float* __restrict__ rw2, const float* __restrict__ rb2,
                       float* __restrict__ out) {
    __shared__ float pm[64], hc[32], hr[32];
    int t = threadIdx.x;    // 64 threads
    if (t < 64) pm[t] = g_pooled[t] * (1.0f / (float)Nn);
    __syncthreads();
    if (t < 32) {
        float sc = cb1[t], sr = rb1[t];
        for (int k = 0; k < 64; k++) {
            sc += cw1[t * 64 + k] * pm[k];
            sr += rw1[t * 64 + k] * pm[k];
        }
        hc[t] = fmaxf(sc, 0.f);
        hr[t] = fmaxf(sr, 0.f);
    }
    __syncthreads();
    if (t < 3) {
        float s = cb2[t];
        for (int k = 0; k < 32; k++) s += cw2[t * 32 + k] * hc[k];
        out[t] = s;
    }
    if (t == 3) {
        float s = rb2[0];
        for (int k = 0; k < 32; k++) s += rw2[k] * hr[k];
        out[3] = s;
    }
}

// ---------------- launch ----------------
extern "C" void kernel_launch(void* const* d_in, const int* in_sizes, int n_in,
                              void* d_out, int out_size) {
    const float* x   = (const float*)d_in[0];
    const int*   ei  = (const int*)d_in[1];
    int E = in_sizes[1] / 2;
    if (E > Emax) E = Emax;
    const int* srcA = ei;
    const int* dstA = ei + E;
    const float* W1  = (const float*)d_in[2];
    const float* a1s = (const float*)d_in[3];
    const float* a1d = (const float*)d_in[4];
    const float* b1  = (const float*)d_in[5];
    const float* W2  = (const float*)d_in[6];
    const float* a2s = (const float*)d_in[7];
    const float* a2d = (const float*)d_in[8];
    const float* b2  = (const float*)d_in[9];
    const float* W3  = (const float*)d_in[10];
    const float* a3s = (const float*)d_in[11];
    const float* a3d = (const float*)d_in[12];
    const float* b3  = (const float*)d_in[13];
    const float* bg  = (const float*)d_in[14];
    const float* bb  = (const float*)d_in[15];
    const float* bm  = (const float*)d_in[16];
    const float* bv  = (const float*)d_in[17];
    const float* cw1 = (const float*)d_in[18];
    const float* cb1 = (const float*)d_in[19];
    const float* cw2 = (const float*)d_in[20];
    const float* cb2 = (const float*)d_in[21];
    const float* rw1 = (const float*)d_in[22];
    const float* rb1 = (const float*)d_in[23];
    const float* rw2 = (const float*)d_in[24];
    const float* rb2 = (const float*)d_in[25];
    float* out = (float*)d_out;

    // CSR build (every call; deterministic work)
    k_init<<<(Nn + 255) / 256, 256>>>();
    k_count<<<(E + 255) / 256, 256>>>(dstA, E);
    k_scan<<<1, 1024>>>(E + Nn);
    k_fill<<<(E + Nn + 255) / 256, 256>>>(srcA, dstA, E);

    int linGrid = (Nn + 127) / 128;
    int aggGrid = (Nn + 7) / 8;

    // layer 1
    k_lin<5, 4><<<linGrid, 128>>>(x, W1, a1s, a1d, 0);
    k_agg<4, true><<<aggGrid, 256>>>(b1, bg + 0,  bb + 0,  bm + 0,  bv + 0,  0);
    // layer 2
    k_lin<64, 4><<<linGrid, 128>>>(nullptr, W2, a2s, a2d, 1);
    k_agg<4, true><<<aggGrid, 256>>>(b2, bg + 64, bb + 64, bm + 64, bv + 64, 1);
    // layer 3
    k_lin<64, 1><<<linGrid, 128>>>(nullptr, W3, a3s, a3d, 2);
    k_agg<1, false><<<aggGrid, 256>>>(b3, bg + 128, bb + 128, bm + 128, bv + 128, 2);

    // pool + heads
    k_pool<<<1024, 64>>>();
    k_head<<<1, 64>>>(cw1, cb1, cw2, cb2, rw1, rb1, rw2, rb2, out);
}